// round 1
// baseline (speedup 1.0000x reference)
#include <cuda_runtime.h>
#include <math_constants.h>

#define BB 4
#define NPT 256
#define KNN 27
#define XCAT 8160
#define LATENT 256

// ---------------- scratch (device globals; no allocation) ----------------
__device__ float  d_xcat[BB * NPT * XCAT];      // layer outputs, concatenated (bb, n, 8160)
__device__ float  d_UV  [BB * NPT * 6144];      // GEMM out per layer: row bn: [0:cout)=U, [cout:2cout)=V
__device__ float  d_M   [BB * NPT * 3072];      // per (bn, o): max_k U[idx] + V
__device__ float  d_Wcat[6144 * 1536];          // [Wd ; Wc - Wd]  (2cout, ch)
__device__ float  d_yt  [BB * NPT * LATENT];    // final GEMM out (bn, o)
__device__ int    d_idx [BB * NPT * KNN];
__device__ double d_S1  [3072];
__device__ double d_S2  [3072];
__device__ float  d_Aff [3072];                 // scale
__device__ float  d_Bias[3072];                 // bias

// ---------------- KNN: warp per point, strict-< argmin (lowest-index ties) ----------------
__global__ void knn_kernel(const float* __restrict__ x) {
    // grid: 4 batches * 32 chunks; block: 256 threads = 8 warps; warp = one point
    int b     = blockIdx.x >> 5;
    int chunk = blockIdx.x & 31;
    int tid   = threadIdx.x;
    int wid   = tid >> 5;
    int lane  = tid & 31;
    int i     = chunk * 8 + wid;

    __shared__ float px[NPT], py[NPT], pz[NPT];
    const float* xb = x + (size_t)b * NPT * 3;
    px[tid] = xb[tid * 3 + 0];
    py[tid] = xb[tid * 3 + 1];
    pz[tid] = xb[tid * 3 + 2];
    __syncthreads();

    float xi = px[i], yi = py[i], zi = pz[i];
    float dloc[8];
    #pragma unroll
    for (int q = 0; q < 8; q++) {
        int j = lane + q * 32;
        float dx = xi - px[j], dy = yi - py[j], dz = zi - pz[j];
        dloc[q] = dx * dx + dy * dy + dz * dz;
    }
    unsigned chosen = 0;  // 8 bits per lane

    for (int s = 0; s < KNN; s++) {
        float bd = CUDART_INF_F;
        int   bj = 0x7fffffff;
        #pragma unroll
        for (int q = 0; q < 8; q++) {
            if (chosen & (1u << q)) continue;
            int j = lane + q * 32;
            float d = dloc[q];
            if (d < bd || (d == bd && j < bj)) { bd = d; bj = j; }
        }
        // butterfly reduce: min by (d, then index)
        #pragma unroll
        for (int off = 16; off > 0; off >>= 1) {
            float od = __shfl_xor_sync(0xffffffffu, bd, off);
            int   oj = __shfl_xor_sync(0xffffffffu, bj, off);
            if (od < bd || (od == bd && oj < bj)) { bd = od; bj = oj; }
        }
        if ((bj & 31) == lane) chosen |= (1u << (bj >> 5));
        if (lane == 0) d_idx[((size_t)(b * NPT + i)) * KNN + s] = bj;
    }
}

// ---------------- Wcat prep: [Wd; Wc - Wd] ----------------
__global__ void prep_wcat(const float* __restrict__ w, int cout, int ch) {
    int idx = blockIdx.x * blockDim.x + threadIdx.x;
    int tot = 2 * cout * ch;
    if (idx >= tot) return;
    int oc = idx / ch, c = idx % ch;
    float v;
    if (oc < cout) {
        v = w[(size_t)oc * 2 * ch + c];
    } else {
        int o = oc - cout;
        v = w[(size_t)o * 2 * ch + ch + c] - w[(size_t)o * 2 * ch + c];
    }
    d_Wcat[idx] = v;
}

// ---------------- GEMM (NT): C[m,n] = sum_k A[m,k]*B[n,k] ----------------
#define BM 64
#define BN 64
#define BKK 16
__global__ __launch_bounds__(256) void gemm_nt(
    const float* __restrict__ A, int lda,
    const float* __restrict__ B, int ldb,
    float* __restrict__ C, int ldc,
    int M, int Nc, int Kd)
{
    __shared__ float As[BKK][BM + 4];
    __shared__ float Bs[BKK][BN + 4];
    int m0 = blockIdx.y * BM, n0 = blockIdx.x * BN;
    int tid = threadIdx.x;
    int tx = tid & 15, ty = tid >> 4;
    float acc[4][4] = {};

    for (int k0 = 0; k0 < Kd; k0 += BKK) {
        #pragma unroll
        for (int t = tid; t < BM * BKK; t += 256) {
            int r = t >> 4, c = t & 15;
            int kk = k0 + c;
            As[c][r] = (kk < Kd) ? A[(size_t)(m0 + r) * lda + kk] : 0.f;
        }
        #pragma unroll
        for (int t = tid; t < BN * BKK; t += 256) {
            int r = t >> 4, c = t & 15;
            int kk = k0 + c, nn = n0 + r;
            Bs[c][r] = (kk < Kd && nn < Nc) ? B[(size_t)nn * ldb + kk] : 0.f;
        }
        __syncthreads();
        #pragma unroll
        for (int kk = 0; kk < BKK; kk++) {
            float a[4], bv[4];
            #pragma unroll
            for (int i = 0; i < 4; i++) a[i] = As[kk][ty * 4 + i];
            #pragma unroll
            for (int j = 0; j < 4; j++) bv[j] = Bs[kk][tx * 4 + j];
            #pragma unroll
            for (int i = 0; i < 4; i++)
                #pragma unroll
                for (int j = 0; j < 4; j++)
                    acc[i][j] += a[i] * bv[j];
        }
        __syncthreads();
    }
    #pragma unroll
    for (int i = 0; i < 4; i++) {
        int m = m0 + ty * 4 + i;
        #pragma unroll
        for (int j = 0; j < 4; j++) {
            int n = n0 + tx * 4 + j;
            if (n < Nc) C[(size_t)m * ldc + n] = acc[i][j];
        }
    }
}

// ---------------- zero stats ----------------
__global__ void zero_stats(int n) {
    int i = blockIdx.x * blockDim.x + threadIdx.x;
    if (i < n) { d_S1[i] = 0.0; d_S2[i] = 0.0; }
}

// ---------------- gather + channel stats + max over k ----------------
__global__ __launch_bounds__(128) void gather_stats_max(int cout, int bn_per_blk) {
    int o = blockIdx.x * 128 + threadIdx.x;
    int bnStart = blockIdx.y * bn_per_blk;
    bool active = (o < cout);
    int twoc = 2 * cout;
    double s1 = 0.0, s2 = 0.0;

    for (int t = 0; t < bn_per_blk; t++) {
        int bn = bnStart + t;
        int b  = bn >> 8;
        const int* ip = d_idx + (size_t)bn * KNN;
        if (!active) continue;
        float v = d_UV[(size_t)bn * twoc + cout + o];
        float mx = -CUDART_INF_F, s = 0.f, ssq = 0.f;
        #pragma unroll
        for (int k = 0; k < KNN; k++) {
            int j = ip[k];
            float u = d_UV[((size_t)(b * NPT + j)) * twoc + o];
            mx = fmaxf(mx, u);
            s += u;
            ssq += u * u;
        }
        d_M[(size_t)bn * cout + o] = mx + v;
        s1 += (double)(s + (float)KNN * v);
        s2 += (double)(ssq + 2.f * v * s + (float)KNN * v * v);
    }
    if (active) {
        atomicAdd(&d_S1[o], s1);
        atomicAdd(&d_S2[o], s2);
    }
}

// ---------------- finalize BN affine ----------------
__global__ void finalize_stats(const float* __restrict__ g, const float* __restrict__ beta,
                               int cout, float invcnt) {
    int o = blockIdx.x * blockDim.x + threadIdx.x;
    if (o >= cout) return;
    float mean = (float)(d_S1[o] * (double)invcnt);
    float var  = (float)(d_S2[o] * (double)invcnt) - mean * mean;
    float a = g[o] / sqrtf(var + 1e-5f);
    d_Aff[o]  = a;
    d_Bias[o] = beta[o] - mean * a;
}

// ---------------- activation + temporal pool + write into xcat ----------------
__global__ void act_pool(int cout, int xoff) {
    int idx = blockIdx.x * blockDim.x + threadIdx.x;
    if (idx >= NPT * cout) return;
    int o = idx % cout, n = idx / cout;
    float a[4];
    float sc = d_Aff[o], bi = d_Bias[o];
    #pragma unroll
    for (int bb = 0; bb < 4; bb++) {
        float m = d_M[(size_t)(bb * NPT + n) * cout + o];
        float y = m * sc + bi;
        a[bb] = (y >= 0.f) ? y : 0.2f * y;
    }
    float tp = 0.5f * (a[0] + a[1]);   // mean over T of batch 0 (reference's tp = mean(exp,axis=1)[0])
    #pragma unroll
    for (int bb = 0; bb < 4; bb++) {
        float* row = d_xcat + (size_t)(bb * NPT + n) * XCAT + xoff;
        row[o] = a[bb];
        row[cout + o] = tp;
    }
}

// ---------------- final-layer stats (per channel over 1024 samples) ----------------
__global__ __launch_bounds__(256) void final_stats() {
    int o = blockIdx.x;          // 256 channels
    int tid = threadIdx.x;
    double s = 0.0, sq = 0.0;
    for (int r = tid; r < BB * NPT; r += 256) {
        float v = d_yt[(size_t)r * LATENT + o];
        s += (double)v;
        sq += (double)v * (double)v;
    }
    __shared__ double sh1[256], sh2[256];
    sh1[tid] = s; sh2[tid] = sq;
    __syncthreads();
    for (int st = 128; st > 0; st >>= 1) {
        if (tid < st) { sh1[tid] += sh1[tid + st]; sh2[tid] += sh2[tid + st]; }
        __syncthreads();
    }
    if (tid == 0) { d_S1[o] = sh1[0]; d_S2[o] = sh2[0]; }
}

// ---------------- write output: (bb, o, n), BN + lrelu ----------------
__global__ void write_out(float* __restrict__ out) {
    int idx = blockIdx.x * blockDim.x + threadIdx.x;
    if (idx >= BB * LATENT * NPT) return;
    int n  = idx % NPT;
    int o  = (idx / NPT) % LATENT;
    int bb = idx / (NPT * LATENT);
    float v = d_yt[(size_t)(bb * NPT + n) * LATENT + o];
    float y = v * d_Aff[o] + d_Bias[o];
    out[idx] = (y >= 0.f) ? y : 0.2f * y;
}

// ---------------- orchestration ----------------
extern "C" void kernel_launch(void* const* d_in, const int* in_sizes, int n_in,
                              void* d_out, int out_size) {
    const float* x = (const float*)d_in[0];
    const float* w[5]; const float* g[5]; const float* bt[5];
    for (int i = 0; i < 5; i++) {
        w[i]  = (const float*)d_in[1 + 3 * i];
        g[i]  = (const float*)d_in[2 + 3 * i];
        bt[i] = (const float*)d_in[3 + 3 * i];
    }
    float* out = (float*)d_out;

    float* xcat_p; float* UV_p; float* Wcat_p; float* yt_p;
    cudaGetSymbolAddress((void**)&xcat_p, d_xcat);
    cudaGetSymbolAddress((void**)&UV_p,   d_UV);
    cudaGetSymbolAddress((void**)&Wcat_p, d_Wcat);
    cudaGetSymbolAddress((void**)&yt_p,   d_yt);

    knn_kernel<<<BB * 32, 256>>>(x);

    const int ch[4]   = {3, 96, 384, 1536};
    const int co[4]   = {48, 192, 768, 3072};
    const int xoff[4] = {0, 96, 480, 2016};

    for (int l = 0; l < 4; l++) {
        int twoc = 2 * co[l];
        int tot = twoc * ch[l];
        prep_wcat<<<(tot + 255) / 256, 256>>>(w[l], co[l], ch[l]);

        const float* Aptr = (l == 0) ? x : (xcat_p + xoff[l - 1]);
        int lda = (l == 0) ? 3 : XCAT;
        dim3 grid((twoc + BN - 1) / BN, (BB * NPT) / BM);
        gemm_nt<<<grid, 256>>>(Aptr, lda, Wcat_p, ch[l], UV_p, twoc, BB * NPT, twoc, ch[l]);

        zero_stats<<<(co[l] + 255) / 256, 256>>>(co[l]);
        dim3 gg((co[l] + 127) / 128, (BB * NPT) / 8);
        gather_stats_max<<<gg, 128>>>(co[l], 8);
        finalize_stats<<<(co[l] + 255) / 256, 256>>>(g[l], bt[l], co[l],
                                                     1.f / (float)(BB * NPT * KNN));
        act_pool<<<(NPT * co[l] + 255) / 256, 256>>>(co[l], xoff[l]);
    }

    // final: y_t(1024,256) = xcat(1024,8160) @ w4^T
    gemm_nt<<<dim3(LATENT / BN, (BB * NPT) / BM), 256>>>(
        xcat_p, XCAT, w[4], XCAT, yt_p, LATENT, BB * NPT, LATENT, XCAT);
    final_stats<<<LATENT, 256>>>();
    finalize_stats<<<1, 256>>>(g[4], bt[4], LATENT, 1.f / (float)(BB * NPT));
    write_out<<<(BB * LATENT * NPT + 255) / 256, 256>>>(out);
}

// round 3
// speedup vs baseline: 1.5894x; 1.5894x over previous
#include <cuda_runtime.h>
#include <cuda_bf16.h>
#include <math_constants.h>
#include <cstdint>

#define BB 4
#define NPT 256
#define KNN 27
#define XCAT 8160
#define LATENT 256

// ---------------- scratch (device globals; no allocation) ----------------
__device__ float         d_xcat[BB * NPT * XCAT];
__device__ float         d_UV  [BB * NPT * 6144];
__device__ float         d_M   [BB * NPT * 3072];
__device__ float         d_yt  [BB * NPT * LATENT];
__device__ float         d_part[12 * BB * NPT * LATENT];
__device__ __nv_bfloat16 d_Abig[1024 * 24512];
__device__ __nv_bfloat16 d_Bbig[6144 * 4608];
__device__ int           d_idx [BB * NPT * KNN];
__device__ double        d_S1  [3072];
__device__ double        d_S2  [3072];
__device__ float         d_Aff [3072];
__device__ float         d_Bias[3072];

__device__ __forceinline__ uint32_t smem_u32(const void* p) {
    return (uint32_t)__cvta_generic_to_shared(p);
}

// ---------------- KNN: warp per point, strict-< argmin ----------------
__global__ void knn_kernel(const float* __restrict__ x) {
    int b     = blockIdx.x >> 5;
    int chunk = blockIdx.x & 31;
    int tid   = threadIdx.x;
    int wid   = tid >> 5;
    int lane  = tid & 31;
    int i     = chunk * 8 + wid;

    __shared__ float px[NPT], py[NPT], pz[NPT];
    const float* xb = x + (size_t)b * NPT * 3;
    px[tid] = xb[tid * 3 + 0];
    py[tid] = xb[tid * 3 + 1];
    pz[tid] = xb[tid * 3 + 2];
    __syncthreads();

    float xi = px[i], yi = py[i], zi = pz[i];
    float dloc[8];
    #pragma unroll
    for (int q = 0; q < 8; q++) {
        int j = lane + q * 32;
        float dx = xi - px[j], dy = yi - py[j], dz = zi - pz[j];
        dloc[q] = dx * dx + dy * dy + dz * dz;
    }
    unsigned chosen = 0;
    for (int s = 0; s < KNN; s++) {
        float bd = CUDART_INF_F;
        int   bj = 0x7fffffff;
        #pragma unroll
        for (int q = 0; q < 8; q++) {
            if (chosen & (1u << q)) continue;
            int j = lane + q * 32;
            float d = dloc[q];
            if (d < bd || (d == bd && j < bj)) { bd = d; bj = j; }
        }
        #pragma unroll
        for (int off = 16; off > 0; off >>= 1) {
            float od = __shfl_xor_sync(0xffffffffu, bd, off);
            int   oj = __shfl_xor_sync(0xffffffffu, bj, off);
            if (od < bd || (od == bd && oj < bj)) { bd = od; bj = oj; }
        }
        if ((bj & 31) == lane) chosen |= (1u << (bj >> 5));
        if (lane == 0) d_idx[((size_t)(b * NPT + i)) * KNN + s] = bj;
    }
}

// ---------------- A conversion: float -> bf16 [hi | lo | hi], zero pad ----------------
__global__ void convA(const float* __restrict__ src, int lda, int K, int Kpad, int M) {
    int idx = blockIdx.x * 256 + threadIdx.x;
    if (idx >= M * Kpad) return;
    int r = idx / Kpad, k = idx % Kpad;
    __nv_bfloat16 o;
    if (k < K) {
        o = __float2bfloat16(src[(size_t)r * lda + k]);
    } else if (k < 2 * K) {
        float f = src[(size_t)r * lda + (k - K)];
        __nv_bfloat16 h = __float2bfloat16(f);
        o = __float2bfloat16(f - __bfloat162float(h));
    } else if (k < 3 * K) {
        o = __float2bfloat16(src[(size_t)r * lda + (k - 2 * K)]);
    } else {
        o = __float2bfloat16(0.f);
    }
    d_Abig[(size_t)r * Kpad + k] = o;
}

// ---------------- B conversion: weights -> bf16 [hi | hi | lo], zero pad ----------------
__global__ void convB(const float* __restrict__ w, int cout, int ch,
                      int K, int Kpad, int Np, int mode) {
    int idx = blockIdx.x * 256 + threadIdx.x;
    if (idx >= Np * Kpad) return;
    int r = idx / Kpad, k = idx % Kpad;
    int kk = (k < K) ? k : (k < 2 * K ? k - K : (k < 3 * K ? k - 2 * K : -1));
    float f = 0.f;
    if (kk >= 0) {
        if (mode) {
            if (r < cout) f = w[(size_t)r * 2 * ch + kk];
            else if (r < 2 * cout)
                f = w[(size_t)(r - cout) * 2 * ch + ch + kk] - w[(size_t)(r - cout) * 2 * ch + kk];
        } else {
            f = w[(size_t)r * K + kk];
        }
    }
    __nv_bfloat16 o;
    if (kk < 0) {
        o = __float2bfloat16(0.f);
    } else if (k < 2 * K) {
        o = __float2bfloat16(f);
    } else {
        __nv_bfloat16 h = __float2bfloat16(f);
        o = __float2bfloat16(f - __bfloat162float(h));
    }
    d_Bbig[(size_t)r * Kpad + k] = o;
}

// ---------------- bf16 HMMA GEMM: C[m,n] = sum_k A[m,k]*B[n,k] ----------------
// Tile 128x128, K-chunk 64, 256 threads = 8 warps (warp tile 32x64).
// SMEM rows 128B (64 bf16), SW128 swizzle. cp.async staged.
#define SW(off) ((off) ^ (((off) >> 3) & 0x70))

__global__ __launch_bounds__(256) void gemm_mma(
    const __nv_bfloat16* __restrict__ A, int ldA,
    const __nv_bfloat16* __restrict__ B, int ldB,
    float* __restrict__ C, int ldc, int Nc,
    int totCh, int chPer, long long splitStride)
{
    __shared__ __align__(128) unsigned char smA[128 * 128];
    __shared__ __align__(128) unsigned char smB[128 * 128];
    uint32_t sbA = smem_u32(smA), sbB = smem_u32(smB);

    int tid  = threadIdx.x;
    int wid  = tid >> 5;
    int lane = tid & 31;
    int m0 = blockIdx.y * 128, n0 = blockIdx.x * 128;
    int split = blockIdx.z;
    C += (long long)split * splitStride;
    int ks = split * chPer;
    int ke = min(ks + chPer, totCh);

    int wm0 = (wid >> 1) * 32;   // warp m offset (4 warps along M)
    int wn0 = (wid & 1) * 64;    // warp n offset (2 warps along N)

    float acc[2][8][4];
    #pragma unroll
    for (int i = 0; i < 2; i++)
        #pragma unroll
        for (int j = 0; j < 8; j++)
            #pragma unroll
            for (int c = 0; c < 4; c++) acc[i][j][c] = 0.f;

    // --- stage chunk ks ---
    {
        const __nv_bfloat16* Ag = A + (size_t)m0 * ldA + (size_t)ks * 64;
        const __nv_bfloat16* Bg = B + (size_t)n0 * ldB + (size_t)ks * 64;
        #pragma unroll
        for (int q = 0; q < 4; q++) {
            int u = tid + q * 256;
            int r = u >> 3, c16 = u & 7;
            uint32_t off = SW((uint32_t)(r * 128 + c16 * 16));
            asm volatile("cp.async.cg.shared.global [%0], [%1], 16;"
                         :: "r"(sbA + off), "l"(Ag + (size_t)r * ldA + c16 * 8));
            asm volatile("cp.async.cg.shared.global [%0], [%1], 16;"
                         :: "r"(sbB + off), "l"(Bg + (size_t)r * ldB + c16 * 8));
        }
        asm volatile("cp.async.commit_group;");
    }

    for (int i = ks; i < ke; i++) {
        asm volatile("cp.async.wait_group 0;");
        __syncthreads();

        #pragma unroll
        for (int kkstep = 0; kkstep < 4; kkstep++) {
            uint32_t ra0[4], ra1[4], rb[4][4];
            int kb = kkstep * 32;
            // A fragments: two m16 tiles
            {
                int r = lane & 7, sel = lane >> 3;
                int m = wm0 + r + (sel & 1) * 8;
                uint32_t off = SW((uint32_t)(m * 128 + kb + (sel >> 1) * 16));
                asm volatile("ldmatrix.sync.aligned.m8n8.x4.shared.b16 {%0,%1,%2,%3}, [%4];"
                             : "=r"(ra0[0]), "=r"(ra0[1]), "=r"(ra0[2]), "=r"(ra0[3])
                             : "r"(sbA + off));
                uint32_t off2 = SW((uint32_t)((m + 16) * 128 + kb + (sel >> 1) * 16));
                asm volatile("ldmatrix.sync.aligned.m8n8.x4.shared.b16 {%0,%1,%2,%3}, [%4];"
                             : "=r"(ra1[0]), "=r"(ra1[1]), "=r"(ra1[2]), "=r"(ra1[3])
                             : "r"(sbA + off2));
            }
            // B fragments: four n16 groups
            #pragma unroll
            for (int g = 0; g < 4; g++) {
                int r = lane & 7, sel = lane >> 3;
                int n = wn0 + g * 16 + r + (sel >> 1) * 8;
                uint32_t off = SW((uint32_t)(n * 128 + kb + (sel & 1) * 16));
                asm volatile("ldmatrix.sync.aligned.m8n8.x4.shared.b16 {%0,%1,%2,%3}, [%4];"
                             : "=r"(rb[g][0]), "=r"(rb[g][1]), "=r"(rb[g][2]), "=r"(rb[g][3])
                             : "r"(sbB + off));
            }
            #pragma unroll
            for (int g = 0; g < 4; g++) {
                #pragma unroll
                for (int half = 0; half < 2; half++) {
                    int j = g * 2 + half;
                    uint32_t b0 = rb[g][half * 2], b1 = rb[g][half * 2 + 1];
                    asm volatile(
                        "mma.sync.aligned.m16n8k16.row.col.f32.bf16.bf16.f32 "
                        "{%0,%1,%2,%3}, {%4,%5,%6,%7}, {%8,%9}, {%0,%1,%2,%3};"
                        : "+f"(acc[0][j][0]), "+f"(acc[0][j][1]),
                          "+f"(acc[0][j][2]), "+f"(acc[0][j][3])
                        : "r"(ra0[0]), "r"(ra0[1]), "r"(ra0[2]), "r"(ra0[3]),
                          "r"(b0), "r"(b1));
                    asm volatile(
                        "mma.sync.aligned.m16n8k16.row.col.f32.bf16.bf16.f32 "
                        "{%0,%1,%2,%3}, {%4,%5,%6,%7}, {%8,%9}, {%0,%1,%2,%3};"
                        : "+f"(acc[1][j][0]), "+f"(acc[1][j][1]),
                          "+f"(acc[1][j][2]), "+f"(acc[1][j][3])
                        : "r"(ra1[0]), "r"(ra1[1]), "r"(ra1[2]), "r"(ra1[3]),
                          "r"(b0), "r"(b1));
                }
            }
        }
        __syncthreads();

        if (i + 1 < ke) {
            const __nv_bfloat16* Ag = A + (size_t)m0 * ldA + (size_t)(i + 1) * 64;
            const __nv_bfloat16* Bg = B + (size_t)n0 * ldB + (size_t)(i + 1) * 64;
            #pragma unroll
            for (int q = 0; q < 4; q++) {
                int u = tid + q * 256;
                int r = u >> 3, c16 = u & 7;
                uint32_t off = SW((uint32_t)(r * 128 + c16 * 16));
                asm volatile("cp.async.cg.shared.global [%0], [%1], 16;"
                             :: "r"(sbA + off), "l"(Ag + (size_t)r * ldA + c16 * 8));
                asm volatile("cp.async.cg.shared.global [%0], [%1], 16;"
                             :: "r"(sbB + off), "l"(Bg + (size_t)r * ldB + c16 * 8));
            }
            asm volatile("cp.async.commit_group;");
        }
    }

    // --- epilogue ---
    #pragma unroll
    for (int mi = 0; mi < 2; mi++) {
        int mlo = m0 + wm0 + mi * 16 + (lane >> 2);
        #pragma unroll
        for (int j = 0; j < 8; j++) {
            int n = n0 + wn0 + j * 8 + (lane & 3) * 2;
            if (n < Nc) {
                float2 v0 = make_float2(acc[mi][j][0], acc[mi][j][1]);
                float2 v1 = make_float2(acc[mi][j][2], acc[mi][j][3]);
                *reinterpret_cast<float2*>(C + (size_t)mlo * ldc + n) = v0;
                *reinterpret_cast<float2*>(C + (size_t)(mlo + 8) * ldc + n) = v1;
            }
        }
    }
}

// ---------------- zero stats ----------------
__global__ void zero_stats(int n) {
    int i = blockIdx.x * blockDim.x + threadIdx.x;
    if (i < n) { d_S1[i] = 0.0; d_S2[i] = 0.0; }
}

// ---------------- gather + channel stats + max over k ----------------
__global__ __launch_bounds__(128) void gather_stats_max(int cout, int bn_per_blk) {
    int o = blockIdx.x * 128 + threadIdx.x;
    int bnStart = blockIdx.y * bn_per_blk;
    bool active = (o < cout);
    int twoc = 2 * cout;
    double s1 = 0.0, s2 = 0.0;

    for (int t = 0; t < bn_per_blk; t++) {
        int bn = bnStart + t;
        int b  = bn >> 8;
        const int* ip = d_idx + (size_t)bn * KNN;
        if (!active) continue;
        float v = d_UV[(size_t)bn * twoc + cout + o];
        float mx = -CUDART_INF_F, s = 0.f, ssq = 0.f;
        #pragma unroll
        for (int k = 0; k < KNN; k++) {
            int j = ip[k];
            float u = d_UV[((size_t)(b * NPT + j)) * twoc + o];
            mx = fmaxf(mx, u);
            s += u;
            ssq += u * u;
        }
        d_M[(size_t)bn * cout + o] = mx + v;
        s1 += (double)(s + (float)KNN * v);
        s2 += (double)(ssq + 2.f * v * s + (float)KNN * v * v);
    }
    if (active) {
        atomicAdd(&d_S1[o], s1);
        atomicAdd(&d_S2[o], s2);
    }
}

// ---------------- finalize BN affine ----------------
__global__ void finalize_stats(const float* __restrict__ g, const float* __restrict__ beta,
                               int cout, float invcnt) {
    int o = blockIdx.x * blockDim.x + threadIdx.x;
    if (o >= cout) return;
    float mean = (float)(d_S1[o] * (double)invcnt);
    float var  = (float)(d_S2[o] * (double)invcnt) - mean * mean;
    float a = g[o] / sqrtf(var + 1e-5f);
    d_Aff[o]  = a;
    d_Bias[o] = beta[o] - mean * a;
}

// ---------------- activation + temporal pool + write into xcat ----------------
__global__ void act_pool(int cout, int xoff) {
    int idx = blockIdx.x * blockDim.x + threadIdx.x;
    if (idx >= NPT * cout) return;
    int o = idx % cout, n = idx / cout;
    float a[4];
    float sc = d_Aff[o], bi = d_Bias[o];
    #pragma unroll
    for (int bb = 0; bb < 4; bb++) {
        float m = d_M[(size_t)(bb * NPT + n) * cout + o];
        float y = m * sc + bi;
        a[bb] = (y >= 0.f) ? y : 0.2f * y;
    }
    float tp = 0.5f * (a[0] + a[1]);
    #pragma unroll
    for (int bb = 0; bb < 4; bb++) {
        float* row = d_xcat + (size_t)(bb * NPT + n) * XCAT + xoff;
        row[o] = a[bb];
        row[cout + o] = tp;
    }
}

// ---------------- split-K reduce ----------------
__global__ void reduce12() {
    int idx = blockIdx.x * 256 + threadIdx.x;
    if (idx >= BB * NPT * LATENT) return;
    float s = 0.f;
    #pragma unroll
    for (int p = 0; p < 12; p++) s += d_part[(size_t)p * BB * NPT * LATENT + idx];
    d_yt[idx] = s;
}

// ---------------- final-layer stats ----------------
__global__ __launch_bounds__(256) void final_stats() {
    int o = blockIdx.x;
    int tid = threadIdx.x;
    double s = 0.0, sq = 0.0;
    for (int r = tid; r < BB * NPT; r += 256) {
        float v = d_yt[(size_t)r * LATENT + o];
        s += (double)v;
        sq += (double)v * (double)v;
    }
    __shared__ double sh1[256], sh2[256];
    sh1[tid] = s; sh2[tid] = sq;
    __syncthreads();
    for (int st = 128; st > 0; st >>= 1) {
        if (tid < st) { sh1[tid] += sh1[tid + st]; sh2[tid] += sh2[tid + st]; }
        __syncthreads();
    }
    if (tid == 0) { d_S1[o] = sh1[0]; d_S2[o] = sh2[0]; }
}

// ---------------- write output: (bb, o, n) ----------------
__global__ void write_out(float* __restrict__ out) {
    int idx = blockIdx.x * blockDim.x + threadIdx.x;
    if (idx >= BB * LATENT * NPT) return;
    int n  = idx % NPT;
    int o  = (idx / NPT) % LATENT;
    int bb = idx / (NPT * LATENT);
    float v = d_yt[(size_t)(bb * NPT + n) * LATENT + o];
    float y = v * d_Aff[o] + d_Bias[o];
    out[idx] = (y >= 0.f) ? y : 0.2f * y;
}

// ---------------- orchestration ----------------
extern "C" void kernel_launch(void* const* d_in, const int* in_sizes, int n_in,
                              void* d_out, int out_size) {
    const float* x = (const float*)d_in[0];
    const float* w[5]; const float* g[5]; const float* bt[5];
    for (int i = 0; i < 5; i++) {
        w[i]  = (const float*)d_in[1 + 3 * i];
        g[i]  = (const float*)d_in[2 + 3 * i];
        bt[i] = (const float*)d_in[3 + 3 * i];
    }
    float* out = (float*)d_out;

    float* xcat_p; float* UV_p; float* yt_p; float* part_p;
    __nv_bfloat16* Abig_p; __nv_bfloat16* Bbig_p;
    cudaGetSymbolAddress((void**)&xcat_p, d_xcat);
    cudaGetSymbolAddress((void**)&UV_p,   d_UV);
    cudaGetSymbolAddress((void**)&yt_p,   d_yt);
    cudaGetSymbolAddress((void**)&part_p, d_part);
    cudaGetSymbolAddress((void**)&Abig_p, d_Abig);
    cudaGetSymbolAddress((void**)&Bbig_p, d_Bbig);

    knn_kernel<<<BB * 32, 256>>>(x);

    const int ch[4]   = {3, 96, 384, 1536};
    const int co[4]   = {48, 192, 768, 3072};
    const int xoff[4] = {0, 96, 480, 2016};
    const int kpad[4] = {64, 320, 1152, 4608};   // 3*ch rounded to 64
    const int npad[4] = {128, 384, 1536, 6144};  // 2*co rounded to 128

    const int M = BB * NPT;  // 1024

    for (int l = 0; l < 4; l++) {
        int twoc = 2 * co[l];
        int Kd = ch[l], Kp = kpad[l], Np = npad[l];
        int totCh = Kp / 64;

        convB<<<((size_t)Np * Kp + 255) / 256, 256>>>(w[l], co[l], ch[l], Kd, Kp, Np, 1);
        const float* Asrc = (l == 0) ? x : (xcat_p + xoff[l - 1]);
        int lda = (l == 0) ? 3 : XCAT;
        convA<<<((size_t)M * Kp + 255) / 256, 256>>>(Asrc, lda, Kd, Kp, M);

        dim3 grid(Np / 128, M / 128, 1);
        gemm_mma<<<grid, 256>>>(Abig_p, Kp, Bbig_p, Kp, UV_p, twoc, twoc, totCh, totCh, 0);

        zero_stats<<<(co[l] + 255) / 256, 256>>>(co[l]);
        dim3 gg((co[l] + 127) / 128, M / 8);
        gather_stats_max<<<gg, 128>>>(co[l], 8);
        finalize_stats<<<(co[l] + 255) / 256, 256>>>(g[l], bt[l], co[l],
                                                     1.f / (float)(M * KNN));
        act_pool<<<(NPT * co[l] + 255) / 256, 256>>>(co[l], xoff[l]);
    }

    // final: y(1024,256) = xcat(1024,8160) @ w4^T, split-K = 12
    {
        int Kd = XCAT, Kp = 24512, totCh = 383, chPer = 32;
        convB<<<((size_t)LATENT * Kp + 255) / 256, 256>>>(w[4], 0, 0, Kd, Kp, LATENT, 0);
        convA<<<((size_t)M * Kp + 255) / 256, 256>>>(xcat_p, XCAT, Kd, Kp, M);
        dim3 grid(LATENT / 128, M / 128, 12);
        gemm_mma<<<grid, 256>>>(Abig_p, Kp, Bbig_p, Kp, part_p, LATENT, LATENT,
                                totCh, chPer, (long long)M * LATENT);
        reduce12<<<(M * LATENT + 255) / 256, 256>>>();
    }
    final_stats<<<LATENT, 256>>>();
    finalize_stats<<<1, 256>>>(g[4], bt[4], LATENT, 1.f / (float)M);
    write_out<<<(BB * LATENT * NPT + 255) / 256, 256>>>(out);
}

// round 5
// speedup vs baseline: 2.3861x; 1.5012x over previous
#include <cuda_runtime.h>
#include <cuda_bf16.h>
#include <math_constants.h>
#include <cstdint>

#define BB 4
#define NPT 256
#define KNN 27
#define XCAT 8160
#define LATENT 256
#define KPFIN 24512

// ---------------- scratch (device globals; zero-init at load, no allocation) ----------------
__device__ float         d_UV  [BB * NPT * 6144];
__device__ float         d_M   [BB * NPT * 3072];
__device__ float         d_yt  [BB * NPT * LATENT];
__device__ float         d_part[12 * BB * NPT * LATENT];
__device__ __nv_bfloat16 d_A0  [1024 * 64];
__device__ __nv_bfloat16 d_A1  [1024 * 320];
__device__ __nv_bfloat16 d_A2  [1024 * 1152];
__device__ __nv_bfloat16 d_A3  [1024 * 4608];
__device__ __nv_bfloat16 d_Afin[1024 * KPFIN];
__device__ __nv_bfloat16 d_Bbig[6144 * 4608];
__device__ int           d_idx [BB * NPT * KNN];
__device__ double        d_S1  [3072];
__device__ double        d_S2  [3072];
__device__ float         d_Aff [3072];
__device__ float         d_Bias[3072];

__device__ __forceinline__ uint32_t smem_u32(const void* p) {
    return (uint32_t)__cvta_generic_to_shared(p);
}

// ---------------- KNN: warp per point, strict-< argmin ----------------
__global__ void knn_kernel(const float* __restrict__ x) {
    int b     = blockIdx.x >> 5;
    int chunk = blockIdx.x & 31;
    int tid   = threadIdx.x;
    int wid   = tid >> 5;
    int lane  = tid & 31;
    int i     = chunk * 8 + wid;

    __shared__ float px[NPT], py[NPT], pz[NPT];
    const float* xb = x + (size_t)b * NPT * 3;
    px[tid] = xb[tid * 3 + 0];
    py[tid] = xb[tid * 3 + 1];
    pz[tid] = xb[tid * 3 + 2];
    __syncthreads();

    float xi = px[i], yi = py[i], zi = pz[i];
    float dloc[8];
    #pragma unroll
    for (int q = 0; q < 8; q++) {
        int j = lane + q * 32;
        float dx = xi - px[j], dy = yi - py[j], dz = zi - pz[j];
        dloc[q] = dx * dx + dy * dy + dz * dz;
    }
    unsigned chosen = 0;
    for (int s = 0; s < KNN; s++) {
        float bd = CUDART_INF_F;
        int   bj = 0x7fffffff;
        #pragma unroll
        for (int q = 0; q < 8; q++) {
            if (chosen & (1u << q)) continue;
            int j = lane + q * 32;
            float d = dloc[q];
            if (d < bd || (d == bd && j < bj)) { bd = d; bj = j; }
        }
        #pragma unroll
        for (int off = 16; off > 0; off >>= 1) {
            float od = __shfl_xor_sync(0xffffffffu, bd, off);
            int   oj = __shfl_xor_sync(0xffffffffu, bj, off);
            if (od < bd || (od == bd && oj < bj)) { bd = od; bj = oj; }
        }
        if ((bj & 31) == lane) chosen |= (1u << (bj >> 5));
        if (lane == 0) d_idx[((size_t)(b * NPT + i)) * KNN + s] = bj;
    }
}

// ---------------- layer-0 A conversion: x(1024,3) -> d_A0 [hi|lo|hi|pad64] ----------------
__global__ void convA0(const float* __restrict__ src) {
    int idx = blockIdx.x * 256 + threadIdx.x;
    if (idx >= 1024 * 64) return;
    int r = idx >> 6, k = idx & 63;
    __nv_bfloat16 o;
    if (k < 3) {
        o = __float2bfloat16(src[r * 3 + k]);
    } else if (k < 6) {
        float f = src[r * 3 + (k - 3)];
        __nv_bfloat16 h = __float2bfloat16(f);
        o = __float2bfloat16(f - __bfloat162float(h));
    } else if (k < 9) {
        o = __float2bfloat16(src[r * 3 + (k - 6)]);
    } else {
        o = __float2bfloat16(0.f);
    }
    d_A0[idx] = o;
}

// ---------------- B conversion: weights -> bf16 [hi | hi | lo], zero pad ----------------
__global__ void convB(const float* __restrict__ w, int cout, int ch,
                      int K, int Kpad, int Np, int mode) {
    int idx = blockIdx.x * 256 + threadIdx.x;
    if (idx >= Np * Kpad) return;
    int r = idx / Kpad, k = idx % Kpad;
    int kk = (k < K) ? k : (k < 2 * K ? k - K : (k < 3 * K ? k - 2 * K : -1));
    float f = 0.f;
    if (kk >= 0) {
        if (mode) {
            if (r < cout) f = w[(size_t)r * 2 * ch + kk];
            else if (r < 2 * cout)
                f = w[(size_t)(r - cout) * 2 * ch + ch + kk] - w[(size_t)(r - cout) * 2 * ch + kk];
        } else {
            f = w[(size_t)r * K + kk];
        }
    }
    __nv_bfloat16 o;
    if (kk < 0) {
        o = __float2bfloat16(0.f);
    } else if (k < 2 * K) {
        o = __float2bfloat16(f);
    } else {
        __nv_bfloat16 h = __float2bfloat16(f);
        o = __float2bfloat16(f - __bfloat162float(h));
    }
    d_Bbig[(size_t)r * Kpad + k] = o;
}

// ---------------- bf16 HMMA GEMM, 3-stage cp.async pipeline ----------------
#define SW(off) ((off) ^ (((off) >> 3) & 0x70))
#define NSTAGE 3
#define STG_BYTES 32768

__device__ __forceinline__ void issue_stage(
    const __nv_bfloat16* Ag, int ldA, const __nv_bfloat16* Bg, int ldB,
    uint32_t sA, uint32_t sB, int tid)
{
    #pragma unroll
    for (int q = 0; q < 4; q++) {
        int u = tid + q * 256;
        int r = u >> 3, c16 = u & 7;
        uint32_t off = SW((uint32_t)(r * 128 + c16 * 16));
        asm volatile("cp.async.cg.shared.global [%0], [%1], 16;"
                     :: "r"(sA + off), "l"(Ag + (size_t)r * ldA + c16 * 8));
        asm volatile("cp.async.cg.shared.global [%0], [%1], 16;"
                     :: "r"(sB + off), "l"(Bg + (size_t)r * ldB + c16 * 8));
    }
}

__global__ __launch_bounds__(256, 1) void gemm_mma(
    const __nv_bfloat16* __restrict__ A, int ldA,
    const __nv_bfloat16* __restrict__ B, int ldB,
    float* __restrict__ C, int ldc, int Nc,
    int totCh, int chPer, long long splitStride)
{
    extern __shared__ __align__(128) unsigned char dyn[];
    uint32_t sb = smem_u32(dyn);

    int tid  = threadIdx.x;
    int wid  = tid >> 5;
    int lane = tid & 31;
    int m0 = blockIdx.y * 128, n0 = blockIdx.x * 128;
    int split = blockIdx.z;
    C += (long long)split * splitStride;
    int ks = split * chPer;
    int ke = min(ks + chPer, totCh);
    int nch = ke - ks;

    int wm0 = (wid >> 1) * 32;
    int wn0 = (wid & 1) * 64;

    float acc[2][8][4];
    #pragma unroll
    for (int i = 0; i < 2; i++)
        #pragma unroll
        for (int j = 0; j < 8; j++)
            #pragma unroll
            for (int c = 0; c < 4; c++) acc[i][j][c] = 0.f;

    const __nv_bfloat16* Abase = A + (size_t)m0 * ldA;
    const __nv_bfloat16* Bbase = B + (size_t)n0 * ldB;

    // prologue: stages 0, 1
    #pragma unroll
    for (int s = 0; s < NSTAGE - 1; s++) {
        if (s < nch)
            issue_stage(Abase + (size_t)(ks + s) * 64, ldA,
                        Bbase + (size_t)(ks + s) * 64, ldB,
                        sb + s * STG_BYTES, sb + s * STG_BYTES + 16384, tid);
        asm volatile("cp.async.commit_group;");
    }

    #pragma unroll 1
    for (int t = 0; t < nch; t++) {
        asm volatile("cp.async.wait_group %0;" :: "n"(NSTAGE - 2));
        __syncthreads();

        {
            int s = t + NSTAGE - 1;
            if (s < nch) {
                uint32_t sbase = sb + (s % NSTAGE) * STG_BYTES;
                issue_stage(Abase + (size_t)(ks + s) * 64, ldA,
                            Bbase + (size_t)(ks + s) * 64, ldB,
                            sbase, sbase + 16384, tid);
            }
            asm volatile("cp.async.commit_group;");
        }

        uint32_t sbA = sb + (t % NSTAGE) * STG_BYTES;
        uint32_t sbB = sbA + 16384;

        #pragma unroll
        for (int kkstep = 0; kkstep < 4; kkstep++) {
            uint32_t ra0[4], ra1[4], rb[4][4];
            int kb = kkstep * 32;
            {
                int r = lane & 7, sel = lane >> 3;
                int m = wm0 + r + (sel & 1) * 8;
                uint32_t off = SW((uint32_t)(m * 128 + kb + (sel >> 1) * 16));
                asm volatile("ldmatrix.sync.aligned.m8n8.x4.shared.b16 {%0,%1,%2,%3}, [%4];"
                             : "=r"(ra0[0]), "=r"(ra0[1]), "=r"(ra0[2]), "=r"(ra0[3])
                             : "r"(sbA + off));
                uint32_t off2 = SW((uint32_t)((m + 16) * 128 + kb + (sel >> 1) * 16));
                asm volatile("ldmatrix.sync.aligned.m8n8.x4.shared.b16 {%0,%1,%2,%3}, [%4];"
                             : "=r"(ra1[0]), "=r"(ra1[1]), "=r"(ra1[2]), "=r"(ra1[3])
                             : "r"(sbA + off2));
            }
            #pragma unroll
            for (int g = 0; g < 4; g++) {
                int r = lane & 7, sel = lane >> 3;
                int n = wn0 + g * 16 + r + (sel >> 1) * 8;
                uint32_t off = SW((uint32_t)(n * 128 + kb + (sel & 1) * 16));
                asm volatile("ldmatrix.sync.aligned.m8n8.x4.shared.b16 {%0,%1,%2,%3}, [%4];"
                             : "=r"(rb[g][0]), "=r"(rb[g][1]), "=r"(rb[g][2]), "=r"(rb[g][3])
                             : "r"(sbB + off));
            }
            #pragma unroll
            for (int g = 0; g < 4; g++) {
                #pragma unroll
                for (int half = 0; half < 2; half++) {
                    int j = g * 2 + half;
                    uint32_t b0 = rb[g][half * 2], b1 = rb[g][half * 2 + 1];
                    asm volatile(
                        "mma.sync.aligned.m16n8k16.row.col.f32.bf16.bf16.f32 "
                        "{%0,%1,%2,%3}, {%4,%5,%6,%7}, {%8,%9}, {%0,%1,%2,%3};"
                        : "+f"(acc[0][j][0]), "+f"(acc[0][j][1]),
                          "+f"(acc[0][j][2]), "+f"(acc[0][j][3])
                        : "r"(ra0[0]), "r"(ra0[1]), "r"(ra0[2]), "r"(ra0[3]),
                          "r"(b0), "r"(b1));
                    asm volatile(
                        "mma.sync.aligned.m16n8k16.row.col.f32.bf16.bf16.f32 "
                        "{%0,%1,%2,%3}, {%4,%5,%6,%7}, {%8,%9}, {%0,%1,%2,%3};"
                        : "+f"(acc[1][j][0]), "+f"(acc[1][j][1]),
                          "+f"(acc[1][j][2]), "+f"(acc[1][j][3])
                        : "r"(ra1[0]), "r"(ra1[1]), "r"(ra1[2]), "r"(ra1[3]),
                          "r"(b0), "r"(b1));
                }
            }
        }
    }

    // --- epilogue ---
    #pragma unroll
    for (int mi = 0; mi < 2; mi++) {
        int mlo = m0 + wm0 + mi * 16 + (lane >> 2);
        #pragma unroll
        for (int j = 0; j < 8; j++) {
            int n = n0 + wn0 + j * 8 + (lane & 3) * 2;
            if (n < Nc) {
                float2 v0 = make_float2(acc[mi][j][0], acc[mi][j][1]);
                float2 v1 = make_float2(acc[mi][j][2], acc[mi][j][3]);
                *reinterpret_cast<float2*>(C + (size_t)mlo * ldc + n) = v0;
                *reinterpret_cast<float2*>(C + (size_t)(mlo + 8) * ldc + n) = v1;
            }
        }
    }
}

// ---------------- zero stats ----------------
__global__ void zero_stats(int n) {
    int i = blockIdx.x * blockDim.x + threadIdx.x;
    if (i < n) { d_S1[i] = 0.0; d_S2[i] = 0.0; }
}

// ---------------- gather + channel stats + max over k ----------------
__global__ __launch_bounds__(128) void gather_stats_max(int cout, int bn_per_blk) {
    int o = blockIdx.x * 128 + threadIdx.x;
    int bnStart = blockIdx.y * bn_per_blk;
    bool active = (o < cout);
    int twoc = 2 * cout;
    double s1 = 0.0, s2 = 0.0;

    for (int t = 0; t < bn_per_blk; t++) {
        int bn = bnStart + t;
        int b  = bn >> 8;
        const int* ip = d_idx + (size_t)bn * KNN;
        if (!active) continue;
        float v = d_UV[(size_t)bn * twoc + cout + o];
        float mx = -CUDART_INF_F, s = 0.f, ssq = 0.f;
        #pragma unroll
        for (int k = 0; k < KNN; k++) {
            int j = ip[k];
            float u = d_UV[((size_t)(b * NPT + j)) * twoc + o];
            mx = fmaxf(mx, u);
            s += u;
            ssq += u * u;
        }
        d_M[(size_t)bn * cout + o] = mx + v;
        s1 += (double)(s + (float)KNN * v);
        s2 += (double)(ssq + 2.f * v * s + (float)KNN * v * v);
    }
    if (active) {
        atomicAdd(&d_S1[o], s1);
        atomicAdd(&d_S2[o], s2);
    }
}

// ---------------- finalize BN affine ----------------
__global__ void finalize_stats(const float* __restrict__ g, const float* __restrict__ beta,
                               int cout, float invcnt) {
    int o = blockIdx.x * blockDim.x + threadIdx.x;
    if (o >= cout) return;
    float mean = (float)(d_S1[o] * (double)invcnt);
    float var  = (float)(d_S2[o] * (double)invcnt) - mean * mean;
    float a = g[o] / sqrtf(var + 1e-5f);
    d_Aff[o]  = a;
    d_Bias[o] = beta[o] - mean * a;
}

// ---------------- activation + temporal pool + write bf16 hi/lo operands ----------------
__global__ void act_pool(int cout, int xoffG, int KpNext, __nv_bfloat16* __restrict__ nextA) {
    int idx = blockIdx.x * blockDim.x + threadIdx.x;
    if (idx >= NPT * cout) return;
    int o = idx % cout, n = idx / cout;
    float a[4];
    float sc = d_Aff[o], bi = d_Bias[o];
    #pragma unroll
    for (int bb = 0; bb < 4; bb++) {
        float m = d_M[(size_t)(bb * NPT + n) * cout + o];
        float y = m * sc + bi;
        a[bb] = (y >= 0.f) ? y : 0.2f * y;
    }
    float tp = 0.5f * (a[0] + a[1]);
    __nv_bfloat16 tph = __float2bfloat16(tp);
    __nv_bfloat16 tpl = __float2bfloat16(tp - __bfloat162float(tph));
    int C2 = 2 * cout;

    #pragma unroll
    for (int bb = 0; bb < 4; bb++) {
        __nv_bfloat16 vh = __float2bfloat16(a[bb]);
        __nv_bfloat16 vl = __float2bfloat16(a[bb] - __bfloat162float(vh));
        size_t r = (size_t)(bb * NPT + n);
        if (nextA) {
            __nv_bfloat16* row = nextA + r * KpNext;
            row[o] = vh;               row[cout + o] = tph;
            row[C2 + o] = vl;          row[C2 + cout + o] = tpl;
            row[2 * C2 + o] = vh;      row[2 * C2 + cout + o] = tph;
        }
        __nv_bfloat16* fr = d_Afin + r * KPFIN;
        fr[xoffG + o] = vh;                 fr[xoffG + cout + o] = tph;
        fr[8160 + xoffG + o] = vl;          fr[8160 + xoffG + cout + o] = tpl;
        fr[16320 + xoffG + o] = vh;         fr[16320 + xoffG + cout + o] = tph;
    }
}

// ---------------- split-K reduce ----------------
__global__ void reduce12() {
    int idx = blockIdx.x * 256 + threadIdx.x;
    if (idx >= BB * NPT * LATENT) return;
    float s = 0.f;
    #pragma unroll
    for (int p = 0; p < 12; p++) s += d_part[(size_t)p * BB * NPT * LATENT + idx];
    d_yt[idx] = s;
}

// ---------------- final-layer stats ----------------
__global__ __launch_bounds__(256) void final_stats() {
    int o = blockIdx.x;
    int tid = threadIdx.x;
    double s = 0.0, sq = 0.0;
    for (int r = tid; r < BB * NPT; r += 256) {
        float v = d_yt[(size_t)r * LATENT + o];
        s += (double)v;
        sq += (double)v * (double)v;
    }
    __shared__ double sh1[256], sh2[256];
    sh1[tid] = s; sh2[tid] = sq;
    __syncthreads();
    for (int st = 128; st > 0; st >>= 1) {
        if (tid < st) { sh1[tid] += sh1[tid + st]; sh2[tid] += sh2[tid + st]; }
        __syncthreads();
    }
    if (tid == 0) { d_S1[o] = sh1[0]; d_S2[o] = sh2[0]; }
}

// ---------------- write output: (bb, o, n) ----------------
__global__ void write_out(float* __restrict__ out) {
    int idx = blockIdx.x * blockDim.x + threadIdx.x;
    if (idx >= BB * LATENT * NPT) return;
    int n  = idx % NPT;
    int o  = (idx / NPT) % LATENT;
    int bb = idx / (NPT * LATENT);
    float v = d_yt[(size_t)(bb * NPT + n) * LATENT + o];
    float y = v * d_Aff[o] + d_Bias[o];
    out[idx] = (y >= 0.f) ? y : 0.2f * y;
}

// ---------------- orchestration ----------------
extern "C" void kernel_launch(void* const* d_in, const int* in_sizes, int n_in,
                              void* d_out, int out_size) {
    const float* x = (const float*)d_in[0];
    const float* w[5]; const float* g[5]; const float* bt[5];
    for (int i = 0; i < 5; i++) {
        w[i]  = (const float*)d_in[1 + 3 * i];
        g[i]  = (const float*)d_in[2 + 3 * i];
        bt[i] = (const float*)d_in[3 + 3 * i];
    }
    float* out = (float*)d_out;

    float* UV_p; float* part_p;
    __nv_bfloat16* Bbig_p; __nv_bfloat16* Afin_p;
    __nv_bfloat16* Abuf[4];
    cudaGetSymbolAddress((void**)&UV_p,   d_UV);
    cudaGetSymbolAddress((void**)&part_p, d_part);
    cudaGetSymbolAddress((void**)&Bbig_p, d_Bbig);
    cudaGetSymbolAddress((void**)&Afin_p, d_Afin);
    cudaGetSymbolAddress((void**)&Abuf[0], d_A0);
    cudaGetSymbolAddress((void**)&Abuf[1], d_A1);
    cudaGetSymbolAddress((void**)&Abuf[2], d_A2);
    cudaGetSymbolAddress((void**)&Abuf[3], d_A3);

    cudaFuncSetAttribute(gemm_mma, cudaFuncAttributeMaxDynamicSharedMemorySize,
                         NSTAGE * STG_BYTES);

    knn_kernel<<<BB * 32, 256>>>(x);
    convA0<<<(1024 * 64 + 255) / 256, 256>>>(x);

    const int ch[4]   = {3, 96, 384, 1536};
    const int co[4]   = {48, 192, 768, 3072};
    const int xoff[4] = {0, 96, 480, 2016};
    const int kpad[5] = {64, 320, 1152, 4608, 0};
    const int npad[4] = {128, 384, 1536, 6144};

    const int M = BB * NPT;  // 1024

    for (int l = 0; l < 4; l++) {
        int twoc = 2 * co[l];
        int Kp = kpad[l], Np = npad[l];
        int totCh = Kp / 64;

        convB<<<((size_t)Np * Kp + 255) / 256, 256>>>(w[l], co[l], ch[l], ch[l], Kp, Np, 1);

        dim3 grid(Np / 128, M / 128, 1);
        gemm_mma<<<grid, 256, NSTAGE * STG_BYTES>>>(
            Abuf[l], Kp, Bbig_p, Kp, UV_p, twoc, twoc, totCh, totCh, 0);

        zero_stats<<<(co[l] + 255) / 256, 256>>>(co[l]);
        dim3 gg((co[l] + 127) / 128, M / 8);
        gather_stats_max<<<gg, 128>>>(co[l], 8);
        finalize_stats<<<(co[l] + 255) / 256, 256>>>(g[l], bt[l], co[l],
                                                     1.f / (float)(M * KNN));
        act_pool<<<(NPT * co[l] + 255) / 256, 256>>>(
            co[l], xoff[l], kpad[l + 1], (l < 3) ? Abuf[l + 1] : nullptr);
    }

    // final: y(1024,256) = xcat(1024,8160) @ w4^T, split-K = 12
    {
        int totCh = KPFIN / 64, chPer = 32;   // 383 chunks, 12 splits
        convB<<<((size_t)LATENT * KPFIN + 255) / 256, 256>>>(w[4], 0, 0, XCAT, KPFIN, LATENT, 0);
        dim3 grid(LATENT / 128, M / 128, 12);
        gemm_mma<<<grid, 256, NSTAGE * STG_BYTES>>>(
            Afin_p, KPFIN, Bbig_p, KPFIN, part_p, LATENT, LATENT,
            totCh, chPer, (long long)M * LATENT);
        reduce12<<<(M * LATENT + 255) / 256, 256>>>();
    }
    final_stats<<<LATENT, 256>>>();
    finalize_stats<<<1, 256>>>(g[4], bt[4], LATENT, 1.f / (float)M);
    write_out<<<(BB * LATENT * NPT + 255) / 256, 256>>>(out);
}